// round 16
// baseline (speedup 1.0000x reference)
#include <cuda_runtime.h>

#define BATCH 4
#define NCTX 4096
#define DM 1024
#define DH 64
#define NT (BATCH * NCTX)

typedef unsigned int u32;
typedef unsigned short u16;

// Pre-split weights (bf16 hi/lo)
__device__ u16 g_Wh[192 * 1024], g_Wl[192 * 1024];   // rows 0-63 Wq, 64-127 Wk, 128-191 Wov
__device__ u16 g_Woh[1024 * 64], g_Wol[1024 * 64];
// Q/K/V pre-split bf16 hi/lo
__device__ u16 g_Qh[NT * DH], g_Ql[NT * DH];
__device__ u16 g_Kh[NT * DH], g_Kl[NT * DH];
__device__ u16 g_Vh[NT * DH], g_Vl[NT * DH];
// attention split-K partials (4 ways) + row sums; combined bf16 result
__device__ float g_Oa[NT * DH], g_Ob[NT * DH], g_Oc[NT * DH], g_Od[NT * DH];
__device__ float g_La[NT], g_Lb[NT], g_Lc[NT], g_Ld[NT];
__device__ u16 g_Ah[NT * DH], g_Al[NT * DH];

// ---------------- helpers ----------------
__device__ __forceinline__ u32 smem_u32(const void* p) {
    u32 a; asm("{ .reg .u64 t; cvta.to.shared.u64 t, %1; cvt.u32.u64 %0, t; }" : "=r"(a) : "l"(p));
    return a;
}
__device__ __forceinline__ u32 sw(u32 off) { return off ^ ((off >> 3) & 0x70); }
__device__ __forceinline__ u32 cvt2(float a, float b) {
    u32 r; asm("cvt.rn.bf16x2.f32 %0, %2, %1;" : "=r"(r) : "f"(a), "f"(b)); return r;
}
__device__ __forceinline__ float2 rec2(u32 h) {
    float2 f; f.x = __uint_as_float(h << 16); f.y = __uint_as_float(h & 0xffff0000u); return f;
}
__device__ __forceinline__ void split2(float x, float y, u32& h, u32& l) {
    h = cvt2(x, y); float2 r = rec2(h); l = cvt2(x - r.x, y - r.y);
}
__device__ __forceinline__ void mma_bf16(float* d, const u32* a, const u32* b) {
    asm volatile("mma.sync.aligned.m16n8k16.row.col.f32.bf16.bf16.f32 "
        "{%0,%1,%2,%3},{%4,%5,%6,%7},{%8,%9},{%0,%1,%2,%3};"
        : "+f"(d[0]), "+f"(d[1]), "+f"(d[2]), "+f"(d[3])
        : "r"(a[0]), "r"(a[1]), "r"(a[2]), "r"(a[3]), "r"(b[0]), "r"(b[1]));
}
__device__ __forceinline__ void ldsm4(u32* r, u32 a) {
    asm volatile("ldmatrix.sync.aligned.m8n8.x4.shared.b16 {%0,%1,%2,%3},[%4];"
        : "=r"(r[0]), "=r"(r[1]), "=r"(r[2]), "=r"(r[3]) : "r"(a));
}
__device__ __forceinline__ void ldsm4t(u32* r, u32 a) {
    asm volatile("ldmatrix.sync.aligned.m8n8.x4.trans.shared.b16 {%0,%1,%2,%3},[%4];"
        : "=r"(r[0]), "=r"(r[1]), "=r"(r[2]), "=r"(r[3]) : "r"(a));
}
__device__ __forceinline__ void stsplit(u32 hb, u32 lb, u32 off, float4 u, float4 v) {
    u32 o = sw(off);
    u32 h0 = cvt2(u.x, u.y), h1 = cvt2(u.z, u.w), h2 = cvt2(v.x, v.y), h3 = cvt2(v.z, v.w);
    float2 r0 = rec2(h0), r1 = rec2(h1), r2 = rec2(h2), r3 = rec2(h3);
    u32 l0 = cvt2(u.x - r0.x, u.y - r0.y), l1 = cvt2(u.z - r1.x, u.w - r1.y);
    u32 l2 = cvt2(v.x - r2.x, v.y - r2.y), l3 = cvt2(v.z - r3.x, v.w - r3.y);
    asm volatile("st.shared.v4.b32 [%0],{%1,%2,%3,%4};" :: "r"(hb + o), "r"(h0), "r"(h1), "r"(h2), "r"(h3));
    asm volatile("st.shared.v4.b32 [%0],{%1,%2,%3,%4};" :: "r"(lb + o), "r"(l0), "r"(l1), "r"(l2), "r"(l3));
}
__device__ __forceinline__ void cpa(u32 dst, const void* src) {
    asm volatile("{.reg .u64 p; cvta.to.global.u64 p, %1; cp.async.cg.shared.global [%0], [p], 16;}"
        :: "r"(dst), "l"(src) : "memory");
}
__device__ __forceinline__ void cpa_commit() { asm volatile("cp.async.commit_group;" ::: "memory"); }
__device__ __forceinline__ void cpa_wait0()  { asm volatile("cp.async.wait_group 0;" ::: "memory"); }
__device__ __forceinline__ void cpa_wait1()  { asm volatile("cp.async.wait_group 1;" ::: "memory"); }

__device__ __forceinline__ u32 bpair_off(int ntp, int kb, int lane) {
    return (u32)((ntp * 16 + ((lane >> 4) * 8) + (lane & 7)) * 128 + kb * 32 + ((lane >> 3) & 1) * 16);
}
__device__ __forceinline__ u32 vpair_off(int htp, int kb, int lane) {
    return (u32)((kb * 16 + (lane & 7) + ((lane >> 3) & 1) * 8) * 128 + htp * 32 + (lane >> 4) * 16);
}

// ---------------------------------------------------------------------------
// Pre-split weights to bf16 hi/lo (one pass; 65536 float4 units)
// ---------------------------------------------------------------------------
__global__ __launch_bounds__(256) void split_w(
    const float* __restrict__ Wq, const float* __restrict__ Wk,
    const float* __restrict__ Wv, const float* __restrict__ Wo)
{
    int j = blockIdx.x * 256 + threadIdx.x;
    const float* src; u16 *dh, *dl;
    if (j < 49152) {
        int e = j * 4;
        int row = e >> 10, col = e & 1023;
        const float* W = (row < 64) ? Wq : ((row < 128) ? Wk : Wv);
        src = W + (size_t)(row & 63) * 1024 + col;
        dh = g_Wh + e; dl = g_Wl + e;
    } else {
        int e = (j - 49152) * 4;
        src = Wo + e;
        dh = g_Woh + e; dl = g_Wol + e;
    }
    float4 v = *(const float4*)src;
    u32 h0, l0, h1, l1;
    split2(v.x, v.y, h0, l0); split2(v.z, v.w, h1, l1);
    *(uint2*)dh = make_uint2(h0, h1);
    *(uint2*)dl = make_uint2(l0, l1);
}

// ---------------------------------------------------------------------------
// QKV: 128x192 tile/CTA, 512 threads (warp grid 8 rows x 2 cols), K in
// 64-chunks, double-buffered smem (A: LDG+split, B: cp.async pure copy).
// ---------------------------------------------------------------------------
__global__ __launch_bounds__(512) void qkv_kernel(
    const float* __restrict__ x,
    const float* __restrict__ bq, const float* __restrict__ bk, const float* __restrict__ bv)
{
    extern __shared__ u16 sm[];
    const u32 base = smem_u32(sm);   // stage s (81920B): ah +0, al +16384, bh +32768, bl +57344
    const int tid = threadIdx.x, wid = tid >> 5, lane = tid & 31;
    const int g = lane >> 2, t4 = lane & 3;
    const int t0 = blockIdx.x * 128;
    const int wr = wid >> 1, wc = wid & 1;
    const int m0 = wr * 16;

    const int ar = tid >> 2, acb = (tid & 3) * 16;     // A: 16 floats/thread
    const float* Ax = x + (size_t)(t0 + ar) * DM + acb;

    float4 xa[4];
    float acc[12][4];
#pragma unroll
    for (int n = 0; n < 12; n++)
#pragma unroll
        for (int e = 0; e < 4; e++) acc[n][e] = 0.0f;

#define QKV_LDGA(c) { _Pragma("unroll") for (int i = 0; i < 4; i++) xa[i] = *(const float4*)&Ax[(c) * 64 + i * 4]; }
#define QKV_STSA(st) { u32 ah_ = base + (st) * 81920, al_ = ah_ + 16384; \
    stsplit(ah_, al_, (u32)(ar * 128 + ((acb >> 3)) * 16), xa[0], xa[1]); \
    stsplit(ah_, al_, (u32)(ar * 128 + ((acb >> 3) + 1) * 16), xa[2], xa[3]); }
#define QKV_CPB(c, st) { u32 bh_ = base + (st) * 81920 + 32768, bl_ = bh_ + 24576; \
    _Pragma("unroll") for (int s = 0; s < 3; s++) { \
        int jj = tid + s * 512; int row = jj >> 3, ch = jj & 7; \
        u32 d = sw((u32)(row * 128 + ch * 16)); \
        const size_t so = (size_t)row * 1024 + (c) * 64 + ch * 8; \
        cpa(bh_ + d, &g_Wh[so]); cpa(bl_ + d, &g_Wl[so]); } }

    // prologue: chunk 0 staged, chunk 1 in regs
    QKV_LDGA(0); QKV_CPB(0, 0); QKV_STSA(0); cpa_commit();
    QKV_LDGA(1);
    cpa_wait0(); __syncthreads();

    for (int c = 0; c < 16; c++) {
        const int cur = c & 1, nxt = cur ^ 1;
        if (c < 15) { QKV_CPB(c + 1, nxt); cpa_commit(); QKV_STSA(nxt); }
        if (c < 14) QKV_LDGA(c + 2);

        const u32 ah_ = base + cur * 81920, al_ = ah_ + 16384;
        const u32 bh_ = ah_ + 32768, bl_ = ah_ + 57344;
#pragma unroll
        for (int kb = 0; kb < 4; kb++) {
            u32 Ah4[4], Al4[4];
            const u32 aoff = (u32)((m0 + (lane & 15)) * 128 + kb * 32 + (lane >> 4) * 16);
            ldsm4(Ah4, ah_ + sw(aoff));
            ldsm4(Al4, al_ + sw(aoff));
#pragma unroll
            for (int ntp = 0; ntp < 6; ntp++) {
                u32 Bh4[4], Bl4[4];
                const u32 bo = bpair_off(wc * 6 + ntp, kb, lane);
                ldsm4(Bh4, bh_ + sw(bo));
                ldsm4(Bl4, bl_ + sw(bo));
                mma_bf16(acc[2 * ntp],     Ah4, &Bh4[0]);
                mma_bf16(acc[2 * ntp],     Ah4, &Bl4[0]);
                mma_bf16(acc[2 * ntp],     Al4, &Bh4[0]);
                mma_bf16(acc[2 * ntp + 1], Ah4, &Bh4[2]);
                mma_bf16(acc[2 * ntp + 1], Ah4, &Bl4[2]);
                mma_bf16(acc[2 * ntp + 1], Al4, &Bh4[2]);
            }
        }
        cpa_wait0(); __syncthreads();
    }

#pragma unroll
    for (int nt = 0; nt < 12; nt++) {
        const int gcol = wc * 96 + nt * 8 + t4 * 2;
        const int sel = gcol >> 6, col = gcol & 63;
        u16* oh = (sel == 0) ? g_Qh : ((sel == 1) ? g_Kh : g_Vh);
        u16* ol = (sel == 0) ? g_Ql : ((sel == 1) ? g_Kl : g_Vl);
        const float* bias = (sel == 0) ? bq : ((sel == 1) ? bk : bv);
        const float scale = (sel == 0) ? 0.03125f : 1.0f;
        const float b0 = bias[col], b1 = bias[col + 1];
        const size_t r0 = (size_t)(t0 + m0 + g) * 64 + col;
        const size_t r1 = r0 + 8 * 64;
        u32 h, l;
        split2((acc[nt][0] + b0) * scale, (acc[nt][1] + b1) * scale, h, l);
        *(u32*)&oh[r0] = h; *(u32*)&ol[r0] = l;
        split2((acc[nt][2] + b0) * scale, (acc[nt][3] + b1) * scale, h, l);
        *(u32*)&oh[r1] = h; *(u32*)&ol[r1] = l;
    }
}

// ---------------------------------------------------------------------------
// Causal flash attention, split-K 4 ways, THREE-stage cp.async pipeline
// (wait_group 1 keeps the next tile's copy in flight during compute).
// FULL split-3 precision (proven rel_err ~1e-5).
// ---------------------------------------------------------------------------
__global__ __launch_bounds__(256) void attn_kernel()
{
    extern __shared__ u16 smA[];
    const u32 base = smem_u32(smA);  // stage st (32768B): kh +0, kl +8192, vh +16384, vl +24576

    const int bid = blockIdx.x;
    const int qt = 31 - (bid >> 4);
    const int b = (bid >> 2) & 3;
    const int spl = bid & 3;
    const int tid = threadIdx.x, wid = tid >> 5, lane = tid & 31;
    const int g = lane >> 2, t4 = lane & 3;
    const int m0g = qt * 128 + wid * 16;
    const size_t qb = (size_t)b * NCTX;

    u32 qh[4][4], ql[4][4];
#pragma unroll
    for (int kb = 0; kb < 4; kb++) {
        const int c0 = kb * 16 + t4 * 2;
        const size_t e00 = (qb + m0g + g) * 64 + c0;
        const size_t e10 = e00 + 8 * 64;
        qh[kb][0] = *(const u32*)&g_Qh[e00];      ql[kb][0] = *(const u32*)&g_Ql[e00];
        qh[kb][1] = *(const u32*)&g_Qh[e10];      ql[kb][1] = *(const u32*)&g_Ql[e10];
        qh[kb][2] = *(const u32*)&g_Qh[e00 + 8];  ql[kb][2] = *(const u32*)&g_Ql[e00 + 8];
        qh[kb][3] = *(const u32*)&g_Qh[e10 + 8];  ql[kb][3] = *(const u32*)&g_Ql[e10 + 8];
    }

    float oacc[8][4];
#pragma unroll
    for (int n = 0; n < 8; n++)
#pragma unroll
        for (int e = 0; e < 4; e++) oacc[n][e] = 0.0f;
    float lr0 = 0.0f, lr1 = 0.0f;

#define ATT_CPKV(i, st) { const int k0_ = (spl + 4 * (i)) * 64; const u32 kb_ = base + (st) * 32768; \
    _Pragma("unroll") for (int s = 0; s < 2; s++) { \
        int jj = tid * 2 + s; int row = jj >> 3, ch = jj & 7; \
        u32 d = sw((u32)(row * 128 + ch * 16)); \
        const size_t so = (qb + k0_ + row) * 64 + ch * 8; \
        cpa(kb_ + d, &g_Kh[so]); cpa(kb_ + 8192 + d, &g_Kl[so]); \
        cpa(kb_ + 16384 + d, &g_Vh[so]); cpa(kb_ + 24576 + d, &g_Vl[so]); } }

    const int totT = 2 * qt + 2;
    const int nT = (totT > spl) ? (totT - spl + 3) / 4 : 0;

    if (nT > 0) {
        // prologue: stage tiles 0 and 1 as separate groups
        ATT_CPKV(0, 0); cpa_commit();
        if (nT > 1) { ATT_CPKV(1, 1); cpa_commit(); }

        for (int i = 0; i < nT; i++) {
            if (i + 1 < nT) cpa_wait1(); else cpa_wait0();   // tile i ready; i+1 may still fly
            __syncthreads();                                  // also fences buffer reuse
            const int cur = i % 3;
            const int k0 = (spl + 4 * i) * 64;

            if (k0 <= m0g + 15) {
                const u32 kh = base + cur * 32768, kl = kh + 8192;
                const u32 vh = kh + 16384, vl = kh + 24576;
                float sacc[8][4];
#pragma unroll
                for (int n = 0; n < 8; n++)
#pragma unroll
                    for (int e = 0; e < 4; e++) sacc[n][e] = 0.0f;
#pragma unroll
                for (int kb = 0; kb < 4; kb++) {
#pragma unroll
                    for (int ntp = 0; ntp < 4; ntp++) {
                        u32 Bh4[4], Bl4[4];
                        const u32 bo = bpair_off(ntp, kb, lane);
                        ldsm4(Bh4, kh + sw(bo));
                        ldsm4(Bl4, kl + sw(bo));
                        mma_bf16(sacc[2 * ntp],     qh[kb], &Bh4[0]);
                        mma_bf16(sacc[2 * ntp],     qh[kb], &Bl4[0]);
                        mma_bf16(sacc[2 * ntp],     ql[kb], &Bh4[0]);
                        mma_bf16(sacc[2 * ntp + 1], qh[kb], &Bh4[2]);
                        mma_bf16(sacc[2 * ntp + 1], qh[kb], &Bl4[2]);
                        mma_bf16(sacc[2 * ntp + 1], ql[kb], &Bh4[2]);
                    }
                }
                const int row0 = m0g + g, row1 = row0 + 8;
#pragma unroll
                for (int nt = 0; nt < 8; nt++) {
                    const int gc0 = k0 + nt * 8 + t4 * 2, gc1 = gc0 + 1;
                    float p00 = (gc0 <= row0) ? __expf(sacc[nt][0]) : 0.0f;
                    float p01 = (gc1 <= row0) ? __expf(sacc[nt][1]) : 0.0f;
                    float p10 = (gc0 <= row1) ? __expf(sacc[nt][2]) : 0.0f;
                    float p11 = (gc1 <= row1) ? __expf(sacc[nt][3]) : 0.0f;
                    lr0 += p00 + p01; lr1 += p10 + p11;
                    sacc[nt][0] = p00; sacc[nt][1] = p01; sacc[nt][2] = p10; sacc[nt][3] = p11;
                }
                u32 ph[4][4], pl[4][4];
#pragma unroll
                for (int kb = 0; kb < 4; kb++) {
                    const int na = 2 * kb, nb = na + 1;
                    split2(sacc[na][0], sacc[na][1], ph[kb][0], pl[kb][0]);
                    split2(sacc[na][2], sacc[na][3], ph[kb][1], pl[kb][1]);
                    split2(sacc[nb][0], sacc[nb][1], ph[kb][2], pl[kb][2]);
                    split2(sacc[nb][2], sacc[nb][3], ph[kb][3], pl[kb][3]);
                }
#pragma unroll
                for (int kb = 0; kb < 4; kb++) {
#pragma unroll
                    for (int htp = 0; htp < 4; htp++) {
                        u32 Vh4[4], Vl4[4];
                        const u32 vo = vpair_off(htp, kb, lane);
                        ldsm4t(Vh4, vh + sw(vo));
                        ldsm4t(Vl4, vl + sw(vo));
                        mma_bf16(oacc[2 * htp],     ph[kb], &Vh4[0]);
                        mma_bf16(oacc[2 * htp],     ph[kb], &Vl4[0]);
                        mma_bf16(oacc[2 * htp],     pl[kb], &Vh4[0]);
                        mma_bf16(oacc[2 * htp + 1], ph[kb], &Vh4[2]);
                        mma_bf16(oacc[2 * htp + 1], ph[kb], &Vl4[2]);
                        mma_bf16(oacc[2 * htp + 1], pl[kb], &Vh4[2]);
                    }
                }
            }
            if (i + 2 < nT) { ATT_CPKV(i + 2, (i + 2) % 3); cpa_commit(); }
        }
    }

    lr0 += __shfl_xor_sync(0xffffffffu, lr0, 1); lr0 += __shfl_xor_sync(0xffffffffu, lr0, 2);
    lr1 += __shfl_xor_sync(0xffffffffu, lr1, 1); lr1 += __shfl_xor_sync(0xffffffffu, lr1, 2);
    float* Op = (spl == 0) ? g_Oa : ((spl == 1) ? g_Ob : ((spl == 2) ? g_Oc : g_Od));
    float* Lp = (spl == 0) ? g_La : ((spl == 1) ? g_Lb : ((spl == 2) ? g_Lc : g_Ld));
    if (t4 == 0) {
        Lp[qb + m0g + g] = lr0;
        Lp[qb + m0g + g + 8] = lr1;
    }
#pragma unroll
    for (int ht = 0; ht < 8; ht++) {
        const int col = ht * 8 + t4 * 2;
        const size_t r0 = (qb + m0g + g) * 64 + col;
        *(float2*)&Op[r0] = make_float2(oacc[ht][0], oacc[ht][1]);
        *(float2*)&Op[r0 + 8 * 64] = make_float2(oacc[ht][2], oacc[ht][3]);
    }
}

// ---------------------------------------------------------------------------
// Combine split-K partials: A = (Oa+Ob+Oc+Od)/(La+Lb+Lc+Ld), as bf16 hi/lo.
// 1024 CTAs, 4 elems/thread (latency-hiding for the pure-bandwidth pass).
// ---------------------------------------------------------------------------
__global__ __launch_bounds__(256) void combine_kernel()
{
    const int j = blockIdx.x * 256 + threadIdx.x;   // 4 elems each
    const int e = j * 4;
    const int row = e >> 6;
    const float inv = 1.0f / (g_La[row] + g_Lb[row] + g_Lc[row] + g_Ld[row]);
    float4 a = *(const float4*)&g_Oa[e];
    float4 b = *(const float4*)&g_Ob[e];
    float4 c = *(const float4*)&g_Oc[e];
    float4 d = *(const float4*)&g_Od[e];
    u32 h0, l0, h1, l1;
    split2((a.x + b.x + c.x + d.x) * inv, (a.y + b.y + c.y + d.y) * inv, h0, l0);
    split2((a.z + b.z + c.z + d.z) * inv, (a.w + b.w + c.w + d.w) * inv, h1, l1);
    *(uint2*)&g_Ah[e] = make_uint2(h0, h1);
    *(uint2*)&g_Al[e] = make_uint2(l0, l1);
}

// ---------------------------------------------------------------------------
// Output projection: 128x128 tile/CTA, K=64 single pass, all-cp.async staging.
// Grid (128, 8), dynamic 64KB smem.
// ---------------------------------------------------------------------------
__global__ __launch_bounds__(256) void proj_kernel(
    const float* __restrict__ bo, float* __restrict__ out)
{
    extern __shared__ u16 smP[];
    const u32 ah = smem_u32(smP), al = ah + 16384;
    const u32 bh = ah + 32768,  bl = ah + 49152;
    const int tid = threadIdx.x, wid = tid >> 5, lane = tid & 31;
    const int g = lane >> 2, t4 = lane & 3;
    const int t0 = blockIdx.x * 128, n0 = blockIdx.y * 128;

#pragma unroll
    for (int s = 0; s < 4; s++) {
        int jj = tid + s * 256;            // 0..1023
        int row = jj >> 3, ch = jj & 7;
        u32 d = sw((u32)(row * 128 + ch * 16));
        const size_t soA = (size_t)(t0 + row) * 64 + ch * 8;
        const size_t soB = (size_t)(n0 + row) * 64 + ch * 8;
        cpa(ah + d, &g_Ah[soA]); cpa(al + d, &g_Al[soA]);
        cpa(bh + d, &g_Woh[soB]); cpa(bl + d, &g_Wol[soB]);
    }
    cpa_commit(); cpa_wait0(); __syncthreads();

    float acc[16][4];
#pragma unroll
    for (int n = 0; n < 16; n++)
#pragma unroll
        for (int e = 0; e < 4; e++) acc[n][e] = 0.0f;

    const int m0 = wid * 16;
#pragma unroll
    for (int kb = 0; kb < 4; kb++) {
        u32 Ah4[4], Al4[4];
        const u32 aoff = (u32)((m0 + (lane & 15)) * 128 + kb * 32 + (lane >> 4) * 16);
        ldsm4(Ah4, ah + sw(aoff));
        ldsm4(Al4, al + sw(aoff));
#pragma unroll
        for (int ntp = 0; ntp < 8; ntp++) {
            u32 Bh4[4], Bl4[4];
            const u32 bo2 = bpair_off(ntp, kb, lane);
            ldsm4(Bh4, bh + sw(bo2));
            ldsm4(Bl4, bl + sw(bo2));
            mma_bf16(acc[2 * ntp],     Ah4, &Bh4[0]);
            mma_bf16(acc[2 * ntp],     Ah4, &Bl4[0]);
            mma_bf16(acc[2 * ntp],     Al4, &Bh4[0]);
            mma_bf16(acc[2 * ntp + 1], Ah4, &Bh4[2]);
            mma_bf16(acc[2 * ntp + 1], Ah4, &Bl4[2]);
            mma_bf16(acc[2 * ntp + 1], Al4, &Bh4[2]);
        }
    }

#pragma unroll
    for (int nt = 0; nt < 16; nt++) {
        const int col = nt * 8 + t4 * 2;
        const float b0 = bo[n0 + col], b1 = bo[n0 + col + 1];
        const size_t r0 = (size_t)(t0 + m0 + g) * DM + n0 + col;
        *(float2*)&out[r0] = make_float2(acc[nt][0] + b0, acc[nt][1] + b1);
        *(float2*)&out[r0 + 8 * DM] = make_float2(acc[nt][2] + b0, acc[nt][3] + b1);
    }
}

// ---------------------------------------------------------------------------
extern "C" void kernel_launch(void* const* d_in, const int* in_sizes, int n_in,
                              void* d_out, int out_size)
{
    const float* x   = (const float*)d_in[0];
    const float* Wq  = (const float*)d_in[1];
    const float* bq  = (const float*)d_in[2];
    const float* Wk  = (const float*)d_in[3];
    const float* bk  = (const float*)d_in[4];
    const float* Wov = (const float*)d_in[5];
    const float* bov = (const float*)d_in[6];
    const float* Wo  = (const float*)d_in[7];
    const float* bo  = (const float*)d_in[8];
    float* out = (float*)d_out;

    cudaFuncSetAttribute(qkv_kernel, cudaFuncAttributeMaxDynamicSharedMemorySize, 163840);
    cudaFuncSetAttribute(attn_kernel, cudaFuncAttributeMaxDynamicSharedMemorySize, 98304);
    cudaFuncSetAttribute(proj_kernel, cudaFuncAttributeMaxDynamicSharedMemorySize, 65536);

    split_w<<<256, 256>>>(Wq, Wk, Wov, Wo);
    qkv_kernel<<<128, 512, 163840>>>(x, bq, bk, bov);
    attn_kernel<<<512, 256, 98304>>>();
    combine_kernel<<<1024, 256>>>();
    proj_kernel<<<dim3(128, 8), 256, 65536>>>(bo, out);
}

// round 17
// speedup vs baseline: 1.4460x; 1.4460x over previous
#include <cuda_runtime.h>

#define BATCH 4
#define NCTX 4096
#define DM 1024
#define DH 64
#define NT (BATCH * NCTX)

typedef unsigned int u32;
typedef unsigned short u16;

// Pre-split weights (bf16 hi/lo)
__device__ u16 g_Wh[192 * 1024], g_Wl[192 * 1024];   // rows 0-63 Wq, 64-127 Wk, 128-191 Wov
__device__ u16 g_Woh[1024 * 64], g_Wol[1024 * 64];
// Q/K/V pre-split bf16 hi/lo
__device__ u16 g_Qh[NT * DH], g_Ql[NT * DH];
__device__ u16 g_Kh[NT * DH], g_Kl[NT * DH];
__device__ u16 g_Vh[NT * DH], g_Vl[NT * DH];
// attention split-K partials (4 ways) + row sums; combined bf16 result
__device__ float g_Oa[NT * DH], g_Ob[NT * DH], g_Oc[NT * DH], g_Od[NT * DH];
__device__ float g_La[NT], g_Lb[NT], g_Lc[NT], g_Ld[NT];
__device__ u16 g_Ah[NT * DH], g_Al[NT * DH];

// ---------------- helpers ----------------
__device__ __forceinline__ u32 smem_u32(const void* p) {
    u32 a; asm("{ .reg .u64 t; cvta.to.shared.u64 t, %1; cvt.u32.u64 %0, t; }" : "=r"(a) : "l"(p));
    return a;
}
__device__ __forceinline__ u32 sw(u32 off) { return off ^ ((off >> 3) & 0x70); }
__device__ __forceinline__ u32 cvt2(float a, float b) {
    u32 r; asm("cvt.rn.bf16x2.f32 %0, %2, %1;" : "=r"(r) : "f"(a), "f"(b)); return r;
}
__device__ __forceinline__ float2 rec2(u32 h) {
    float2 f; f.x = __uint_as_float(h << 16); f.y = __uint_as_float(h & 0xffff0000u); return f;
}
__device__ __forceinline__ void split2(float x, float y, u32& h, u32& l) {
    h = cvt2(x, y); float2 r = rec2(h); l = cvt2(x - r.x, y - r.y);
}
__device__ __forceinline__ void mma_bf16(float* d, const u32* a, const u32* b) {
    asm volatile("mma.sync.aligned.m16n8k16.row.col.f32.bf16.bf16.f32 "
        "{%0,%1,%2,%3},{%4,%5,%6,%7},{%8,%9},{%0,%1,%2,%3};"
        : "+f"(d[0]), "+f"(d[1]), "+f"(d[2]), "+f"(d[3])
        : "r"(a[0]), "r"(a[1]), "r"(a[2]), "r"(a[3]), "r"(b[0]), "r"(b[1]));
}
__device__ __forceinline__ void ldsm4(u32* r, u32 a) {
    asm volatile("ldmatrix.sync.aligned.m8n8.x4.shared.b16 {%0,%1,%2,%3},[%4];"
        : "=r"(r[0]), "=r"(r[1]), "=r"(r[2]), "=r"(r[3]) : "r"(a));
}
__device__ __forceinline__ void ldsm4t(u32* r, u32 a) {
    asm volatile("ldmatrix.sync.aligned.m8n8.x4.trans.shared.b16 {%0,%1,%2,%3},[%4];"
        : "=r"(r[0]), "=r"(r[1]), "=r"(r[2]), "=r"(r[3]) : "r"(a));
}
__device__ __forceinline__ void stsplit(u32 hb, u32 lb, u32 off, float4 u, float4 v) {
    u32 o = sw(off);
    u32 h0 = cvt2(u.x, u.y), h1 = cvt2(u.z, u.w), h2 = cvt2(v.x, v.y), h3 = cvt2(v.z, v.w);
    float2 r0 = rec2(h0), r1 = rec2(h1), r2 = rec2(h2), r3 = rec2(h3);
    u32 l0 = cvt2(u.x - r0.x, u.y - r0.y), l1 = cvt2(u.z - r1.x, u.w - r1.y);
    u32 l2 = cvt2(v.x - r2.x, v.y - r2.y), l3 = cvt2(v.z - r3.x, v.w - r3.y);
    asm volatile("st.shared.v4.b32 [%0],{%1,%2,%3,%4};" :: "r"(hb + o), "r"(h0), "r"(h1), "r"(h2), "r"(h3));
    asm volatile("st.shared.v4.b32 [%0],{%1,%2,%3,%4};" :: "r"(lb + o), "r"(l0), "r"(l1), "r"(l2), "r"(l3));
}
__device__ __forceinline__ void cpa(u32 dst, const void* src) {
    asm volatile("{.reg .u64 p; cvta.to.global.u64 p, %1; cp.async.cg.shared.global [%0], [p], 16;}"
        :: "r"(dst), "l"(src) : "memory");
}
__device__ __forceinline__ void cpa_commit() { asm volatile("cp.async.commit_group;" ::: "memory"); }
__device__ __forceinline__ void cpa_wait0()  { asm volatile("cp.async.wait_group 0;" ::: "memory"); }

__device__ __forceinline__ u32 bpair_off(int ntp, int kb, int lane) {
    return (u32)((ntp * 16 + ((lane >> 4) * 8) + (lane & 7)) * 128 + kb * 32 + ((lane >> 3) & 1) * 16);
}
__device__ __forceinline__ u32 vpair_off(int htp, int kb, int lane) {
    return (u32)((kb * 16 + (lane & 7) + ((lane >> 3) & 1) * 8) * 128 + htp * 32 + (lane >> 4) * 16);
}

// ---------------------------------------------------------------------------
// Pre-split weights to bf16 hi/lo (one pass; 65536 float4 units)
// ---------------------------------------------------------------------------
__global__ __launch_bounds__(256) void split_w(
    const float* __restrict__ Wq, const float* __restrict__ Wk,
    const float* __restrict__ Wv, const float* __restrict__ Wo)
{
    int j = blockIdx.x * 256 + threadIdx.x;
    const float* src; u16 *dh, *dl;
    if (j < 49152) {
        int e = j * 4;
        int row = e >> 10, col = e & 1023;
        const float* W = (row < 64) ? Wq : ((row < 128) ? Wk : Wv);
        src = W + (size_t)(row & 63) * 1024 + col;
        dh = g_Wh + e; dl = g_Wl + e;
    } else {
        int e = (j - 49152) * 4;
        src = Wo + e;
        dh = g_Woh + e; dl = g_Wol + e;
    }
    float4 v = *(const float4*)src;
    u32 h0, l0, h1, l1;
    split2(v.x, v.y, h0, l0); split2(v.z, v.w, h1, l1);
    *(uint2*)dh = make_uint2(h0, h1);
    *(uint2*)dl = make_uint2(l0, l1);
}

// ---------------------------------------------------------------------------
// QKV: 128x192 tile/CTA, 512 threads, warp grid 4 rows x 4 cols (each warp
// 32 rows x 48 cols, two m16 A-tiles) — cuts ldsm traffic 29% vs 8x2.
// K in 64-chunks, double-buffered smem (A: LDG+split, B: cp.async).
// ---------------------------------------------------------------------------
__global__ __launch_bounds__(512) void qkv_kernel(
    const float* __restrict__ x,
    const float* __restrict__ bq, const float* __restrict__ bk, const float* __restrict__ bv)
{
    extern __shared__ u16 sm[];
    const u32 base = smem_u32(sm);   // stage s (81920B): ah +0, al +16384, bh +32768, bl +57344
    const int tid = threadIdx.x, wid = tid >> 5, lane = tid & 31;
    const int g = lane >> 2, t4 = lane & 3;
    const int t0 = blockIdx.x * 128;
    const int wr = wid >> 2, wc = wid & 3;   // 4x4 warp grid
    const int m0 = wr * 32;                  // 32 rows per warp (2 m16 tiles)

    const int ar = tid >> 2, acb = (tid & 3) * 16;     // A: 16 floats/thread
    const float* Ax = x + (size_t)(t0 + ar) * DM + acb;

    float4 xa[4];
    float acc[2][6][4];
#pragma unroll
    for (int mt = 0; mt < 2; mt++)
#pragma unroll
        for (int n = 0; n < 6; n++)
#pragma unroll
            for (int e = 0; e < 4; e++) acc[mt][n][e] = 0.0f;

#define QKV_LDGA(c) { _Pragma("unroll") for (int i = 0; i < 4; i++) xa[i] = *(const float4*)&Ax[(c) * 64 + i * 4]; }
#define QKV_STSA(st) { u32 ah_ = base + (st) * 81920, al_ = ah_ + 16384; \
    stsplit(ah_, al_, (u32)(ar * 128 + ((acb >> 3)) * 16), xa[0], xa[1]); \
    stsplit(ah_, al_, (u32)(ar * 128 + ((acb >> 3) + 1) * 16), xa[2], xa[3]); }
#define QKV_CPB(c, st) { u32 bh_ = base + (st) * 81920 + 32768, bl_ = bh_ + 24576; \
    _Pragma("unroll") for (int s = 0; s < 3; s++) { \
        int jj = tid + s * 512; int row = jj >> 3, ch = jj & 7; \
        u32 d = sw((u32)(row * 128 + ch * 16)); \
        const size_t so = (size_t)row * 1024 + (c) * 64 + ch * 8; \
        cpa(bh_ + d, &g_Wh[so]); cpa(bl_ + d, &g_Wl[so]); } }

    // prologue: chunk 0 staged, chunk 1 in regs
    QKV_LDGA(0); QKV_CPB(0, 0); QKV_STSA(0); cpa_commit();
    QKV_LDGA(1);
    cpa_wait0(); __syncthreads();

    for (int c = 0; c < 16; c++) {
        const int cur = c & 1, nxt = cur ^ 1;
        if (c < 15) { QKV_CPB(c + 1, nxt); cpa_commit(); QKV_STSA(nxt); }
        if (c < 14) QKV_LDGA(c + 2);

        const u32 ah_ = base + cur * 81920, al_ = ah_ + 16384;
        const u32 bh_ = ah_ + 32768, bl_ = ah_ + 57344;
#pragma unroll
        for (int kb = 0; kb < 4; kb++) {
            u32 Ah4[2][4], Al4[2][4];
#pragma unroll
            for (int mt = 0; mt < 2; mt++) {
                const u32 aoff = (u32)((m0 + mt * 16 + (lane & 15)) * 128 + kb * 32 + (lane >> 4) * 16);
                ldsm4(Ah4[mt], ah_ + sw(aoff));
                ldsm4(Al4[mt], al_ + sw(aoff));
            }
#pragma unroll
            for (int ntp = 0; ntp < 3; ntp++) {
                u32 Bh4[4], Bl4[4];
                const u32 bo = bpair_off(wc * 3 + ntp, kb, lane);
                ldsm4(Bh4, bh_ + sw(bo));
                ldsm4(Bl4, bl_ + sw(bo));
#pragma unroll
                for (int mt = 0; mt < 2; mt++) {
                    mma_bf16(acc[mt][2 * ntp],     Ah4[mt], &Bh4[0]);
                    mma_bf16(acc[mt][2 * ntp],     Ah4[mt], &Bl4[0]);
                    mma_bf16(acc[mt][2 * ntp],     Al4[mt], &Bh4[0]);
                    mma_bf16(acc[mt][2 * ntp + 1], Ah4[mt], &Bh4[2]);
                    mma_bf16(acc[mt][2 * ntp + 1], Ah4[mt], &Bl4[2]);
                    mma_bf16(acc[mt][2 * ntp + 1], Al4[mt], &Bh4[2]);
                }
            }
        }
        cpa_wait0(); __syncthreads();
    }

#pragma unroll
    for (int mt = 0; mt < 2; mt++)
#pragma unroll
    for (int nt = 0; nt < 6; nt++) {
        const int gcol = wc * 48 + nt * 8 + t4 * 2;
        const int sel = gcol >> 6, col = gcol & 63;
        u16* oh = (sel == 0) ? g_Qh : ((sel == 1) ? g_Kh : g_Vh);
        u16* ol = (sel == 0) ? g_Ql : ((sel == 1) ? g_Kl : g_Vl);
        const float* bias = (sel == 0) ? bq : ((sel == 1) ? bk : bv);
        const float scale = (sel == 0) ? 0.03125f : 1.0f;
        const float b0 = bias[col], b1 = bias[col + 1];
        const size_t r0 = (size_t)(t0 + m0 + mt * 16 + g) * 64 + col;
        const size_t r1 = r0 + 8 * 64;
        u32 h, l;
        split2((acc[mt][nt][0] + b0) * scale, (acc[mt][nt][1] + b1) * scale, h, l);
        *(u32*)&oh[r0] = h; *(u32*)&ol[r0] = l;
        split2((acc[mt][nt][2] + b0) * scale, (acc[mt][nt][3] + b1) * scale, h, l);
        *(u32*)&oh[r1] = h; *(u32*)&ol[r1] = l;
    }
}

// ---------------------------------------------------------------------------
// Causal flash attention, split-K 4 ways, 2-stage cp.async (64KB, 3 CTAs/SM).
// FULL split-3 precision (proven rel_err ~1e-5).  [reverted to R15 form]
// ---------------------------------------------------------------------------
__global__ __launch_bounds__(256) void attn_kernel()
{
    extern __shared__ u16 smA[];
    const u32 base = smem_u32(smA);  // stage st (32768B): kh +0, kl +8192, vh +16384, vl +24576

    const int bid = blockIdx.x;
    const int qt = 31 - (bid >> 4);
    const int b = (bid >> 2) & 3;
    const int spl = bid & 3;
    const int tid = threadIdx.x, wid = tid >> 5, lane = tid & 31;
    const int g = lane >> 2, t4 = lane & 3;
    const int m0g = qt * 128 + wid * 16;
    const size_t qb = (size_t)b * NCTX;

    u32 qh[4][4], ql[4][4];
#pragma unroll
    for (int kb = 0; kb < 4; kb++) {
        const int c0 = kb * 16 + t4 * 2;
        const size_t e00 = (qb + m0g + g) * 64 + c0;
        const size_t e10 = e00 + 8 * 64;
        qh[kb][0] = *(const u32*)&g_Qh[e00];      ql[kb][0] = *(const u32*)&g_Ql[e00];
        qh[kb][1] = *(const u32*)&g_Qh[e10];      ql[kb][1] = *(const u32*)&g_Ql[e10];
        qh[kb][2] = *(const u32*)&g_Qh[e00 + 8];  ql[kb][2] = *(const u32*)&g_Ql[e00 + 8];
        qh[kb][3] = *(const u32*)&g_Qh[e10 + 8];  ql[kb][3] = *(const u32*)&g_Ql[e10 + 8];
    }

    float oacc[8][4];
#pragma unroll
    for (int n = 0; n < 8; n++)
#pragma unroll
        for (int e = 0; e < 4; e++) oacc[n][e] = 0.0f;
    float lr0 = 0.0f, lr1 = 0.0f;

#define ATT_CPKV(i, st) { const int k0_ = (spl + 4 * (i)) * 64; const u32 kb_ = base + (st) * 32768; \
    _Pragma("unroll") for (int s = 0; s < 2; s++) { \
        int jj = tid * 2 + s; int row = jj >> 3, ch = jj & 7; \
        u32 d = sw((u32)(row * 128 + ch * 16)); \
        const size_t so = (qb + k0_ + row) * 64 + ch * 8; \
        cpa(kb_ + d, &g_Kh[so]); cpa(kb_ + 8192 + d, &g_Kl[so]); \
        cpa(kb_ + 16384 + d, &g_Vh[so]); cpa(kb_ + 24576 + d, &g_Vl[so]); } }

    const int totT = 2 * qt + 2;
    const int nT = (totT > spl) ? (totT - spl + 3) / 4 : 0;

    if (nT > 0) {
        ATT_CPKV(0, 0); cpa_commit();
        cpa_wait0(); __syncthreads();

        for (int i = 0; i < nT; i++) {
            const int cur = i & 1;
            if (i + 1 < nT) { ATT_CPKV(i + 1, cur ^ 1); cpa_commit(); }
            const int k0 = (spl + 4 * i) * 64;

            if (k0 <= m0g + 15) {
                const u32 kh = base + cur * 32768, kl = kh + 8192;
                const u32 vh = kh + 16384, vl = kh + 24576;
                float sacc[8][4];
#pragma unroll
                for (int n = 0; n < 8; n++)
#pragma unroll
                    for (int e = 0; e < 4; e++) sacc[n][e] = 0.0f;
#pragma unroll
                for (int kb = 0; kb < 4; kb++) {
#pragma unroll
                    for (int ntp = 0; ntp < 4; ntp++) {
                        u32 Bh4[4], Bl4[4];
                        const u32 bo = bpair_off(ntp, kb, lane);
                        ldsm4(Bh4, kh + sw(bo));
                        ldsm4(Bl4, kl + sw(bo));
                        mma_bf16(sacc[2 * ntp],     qh[kb], &Bh4[0]);
                        mma_bf16(sacc[2 * ntp],     qh[kb], &Bl4[0]);
                        mma_bf16(sacc[2 * ntp],     ql[kb], &Bh4[0]);
                        mma_bf16(sacc[2 * ntp + 1], qh[kb], &Bh4[2]);
                        mma_bf16(sacc[2 * ntp + 1], qh[kb], &Bl4[2]);
                        mma_bf16(sacc[2 * ntp + 1], ql[kb], &Bh4[2]);
                    }
                }
                const int row0 = m0g + g, row1 = row0 + 8;
#pragma unroll
                for (int nt = 0; nt < 8; nt++) {
                    const int gc0 = k0 + nt * 8 + t4 * 2, gc1 = gc0 + 1;
                    float p00 = (gc0 <= row0) ? __expf(sacc[nt][0]) : 0.0f;
                    float p01 = (gc1 <= row0) ? __expf(sacc[nt][1]) : 0.0f;
                    float p10 = (gc0 <= row1) ? __expf(sacc[nt][2]) : 0.0f;
                    float p11 = (gc1 <= row1) ? __expf(sacc[nt][3]) : 0.0f;
                    lr0 += p00 + p01; lr1 += p10 + p11;
                    sacc[nt][0] = p00; sacc[nt][1] = p01; sacc[nt][2] = p10; sacc[nt][3] = p11;
                }
                u32 ph[4][4], pl[4][4];
#pragma unroll
                for (int kb = 0; kb < 4; kb++) {
                    const int na = 2 * kb, nb = na + 1;
                    split2(sacc[na][0], sacc[na][1], ph[kb][0], pl[kb][0]);
                    split2(sacc[na][2], sacc[na][3], ph[kb][1], pl[kb][1]);
                    split2(sacc[nb][0], sacc[nb][1], ph[kb][2], pl[kb][2]);
                    split2(sacc[nb][2], sacc[nb][3], ph[kb][3], pl[kb][3]);
                }
#pragma unroll
                for (int kb = 0; kb < 4; kb++) {
#pragma unroll
                    for (int htp = 0; htp < 4; htp++) {
                        u32 Vh4[4], Vl4[4];
                        const u32 vo = vpair_off(htp, kb, lane);
                        ldsm4t(Vh4, vh + sw(vo));
                        ldsm4t(Vl4, vl + sw(vo));
                        mma_bf16(oacc[2 * htp],     ph[kb], &Vh4[0]);
                        mma_bf16(oacc[2 * htp],     ph[kb], &Vl4[0]);
                        mma_bf16(oacc[2 * htp],     pl[kb], &Vh4[0]);
                        mma_bf16(oacc[2 * htp + 1], ph[kb], &Vh4[2]);
                        mma_bf16(oacc[2 * htp + 1], ph[kb], &Vl4[2]);
                        mma_bf16(oacc[2 * htp + 1], pl[kb], &Vh4[2]);
                    }
                }
            }
            cpa_wait0(); __syncthreads();
        }
    }

    lr0 += __shfl_xor_sync(0xffffffffu, lr0, 1); lr0 += __shfl_xor_sync(0xffffffffu, lr0, 2);
    lr1 += __shfl_xor_sync(0xffffffffu, lr1, 1); lr1 += __shfl_xor_sync(0xffffffffu, lr1, 2);
    float* Op = (spl == 0) ? g_Oa : ((spl == 1) ? g_Ob : ((spl == 2) ? g_Oc : g_Od));
    float* Lp = (spl == 0) ? g_La : ((spl == 1) ? g_Lb : ((spl == 2) ? g_Lc : g_Ld));
    if (t4 == 0) {
        Lp[qb + m0g + g] = lr0;
        Lp[qb + m0g + g + 8] = lr1;
    }
#pragma unroll
    for (int ht = 0; ht < 8; ht++) {
        const int col = ht * 8 + t4 * 2;
        const size_t r0 = (qb + m0g + g) * 64 + col;
        *(float2*)&Op[r0] = make_float2(oacc[ht][0], oacc[ht][1]);
        *(float2*)&Op[r0 + 8 * 64] = make_float2(oacc[ht][2], oacc[ht][3]);
    }
}

// ---------------------------------------------------------------------------
// Combine split-K partials: A = (Oa+Ob+Oc+Od)/(La+Lb+Lc+Ld), as bf16 hi/lo.
// 1024 CTAs, 4 elems/thread.
// ---------------------------------------------------------------------------
__global__ __launch_bounds__(256) void combine_kernel()
{
    const int j = blockIdx.x * 256 + threadIdx.x;   // 4 elems each
    const int e = j * 4;
    const int row = e >> 6;
    const float inv = 1.0f / (g_La[row] + g_Lb[row] + g_Lc[row] + g_Ld[row]);
    float4 a = *(const float4*)&g_Oa[e];
    float4 b = *(const float4*)&g_Ob[e];
    float4 c = *(const float4*)&g_Oc[e];
    float4 d = *(const float4*)&g_Od[e];
    u32 h0, l0, h1, l1;
    split2((a.x + b.x + c.x + d.x) * inv, (a.y + b.y + c.y + d.y) * inv, h0, l0);
    split2((a.z + b.z + c.z + d.z) * inv, (a.w + b.w + c.w + d.w) * inv, h1, l1);
    *(uint2*)&g_Ah[e] = make_uint2(h0, h1);
    *(uint2*)&g_Al[e] = make_uint2(l0, l1);
}

// ---------------------------------------------------------------------------
// Output projection: 128x128 tile/CTA, K=64 single pass, all-cp.async staging.
// Grid (128, 8), dynamic 64KB smem.
// ---------------------------------------------------------------------------
__global__ __launch_bounds__(256) void proj_kernel(
    const float* __restrict__ bo, float* __restrict__ out)
{
    extern __shared__ u16 smP[];
    const u32 ah = smem_u32(smP), al = ah + 16384;
    const u32 bh = ah + 32768,  bl = ah + 49152;
    const int tid = threadIdx.x, wid = tid >> 5, lane = tid & 31;
    const int g = lane >> 2, t4 = lane & 3;
    const int t0 = blockIdx.x * 128, n0 = blockIdx.y * 128;

#pragma unroll
    for (int s = 0; s < 4; s++) {
        int jj = tid + s * 256;            // 0..1023
        int row = jj >> 3, ch = jj & 7;
        u32 d = sw((u32)(row * 128 + ch * 16));
        const size_t soA = (size_t)(t0 + row) * 64 + ch * 8;
        const size_t soB = (size_t)(n0 + row) * 64 + ch * 8;
        cpa(ah + d, &g_Ah[soA]); cpa(al + d, &g_Al[soA]);
        cpa(bh + d, &g_Woh[soB]); cpa(bl + d, &g_Wol[soB]);
    }
    cpa_commit(); cpa_wait0(); __syncthreads();

    float acc[16][4];
#pragma unroll
    for (int n = 0; n < 16; n++)
#pragma unroll
        for (int e = 0; e < 4; e++) acc[n][e] = 0.0f;

    const int m0 = wid * 16;
#pragma unroll
    for (int kb = 0; kb < 4; kb++) {
        u32 Ah4[4], Al4[4];
        const u32 aoff = (u32)((m0 + (lane & 15)) * 128 + kb * 32 + (lane >> 4) * 16);
        ldsm4(Ah4, ah + sw(aoff));
        ldsm4(Al4, al + sw(aoff));
#pragma unroll
        for (int ntp = 0; ntp < 8; ntp++) {
            u32 Bh4[4], Bl4[4];
            const u32 bo2 = bpair_off(ntp, kb, lane);
            ldsm4(Bh4, bh + sw(bo2));
            ldsm4(Bl4, bl + sw(bo2));
            mma_bf16(acc[2 * ntp],     Ah4, &Bh4[0]);
            mma_bf16(acc[2 * ntp],     Ah4, &Bl4[0]);
            mma_bf16(acc[2 * ntp],     Al4, &Bh4[0]);
            mma_bf16(acc[2 * ntp + 1], Ah4, &Bh4[2]);
            mma_bf16(acc[2 * ntp + 1], Ah4, &Bl4[2]);
            mma_bf16(acc[2 * ntp + 1], Al4, &Bh4[2]);
        }
    }

#pragma unroll
    for (int nt = 0; nt < 16; nt++) {
        const int col = nt * 8 + t4 * 2;
        const float b0 = bo[n0 + col], b1 = bo[n0 + col + 1];
        const size_t r0 = (size_t)(t0 + m0 + g) * DM + n0 + col;
        *(float2*)&out[r0] = make_float2(acc[nt][0] + b0, acc[nt][1] + b1);
        *(float2*)&out[r0 + 8 * DM] = make_float2(acc[nt][2] + b0, acc[nt][3] + b1);
    }
}

// ---------------------------------------------------------------------------
extern "C" void kernel_launch(void* const* d_in, const int* in_sizes, int n_in,
                              void* d_out, int out_size)
{
    const float* x   = (const float*)d_in[0];
    const float* Wq  = (const float*)d_in[1];
    const float* bq  = (const float*)d_in[2];
    const float* Wk  = (const float*)d_in[3];
    const float* bk  = (const float*)d_in[4];
    const float* Wov = (const float*)d_in[5];
    const float* bov = (const float*)d_in[6];
    const float* Wo  = (const float*)d_in[7];
    const float* bo  = (const float*)d_in[8];
    float* out = (float*)d_out;

    cudaFuncSetAttribute(qkv_kernel, cudaFuncAttributeMaxDynamicSharedMemorySize, 163840);
    cudaFuncSetAttribute(attn_kernel, cudaFuncAttributeMaxDynamicSharedMemorySize, 65536);
    cudaFuncSetAttribute(proj_kernel, cudaFuncAttributeMaxDynamicSharedMemorySize, 65536);

    split_w<<<256, 256>>>(Wq, Wk, Wov, Wo);
    qkv_kernel<<<128, 512, 163840>>>(x, bq, bk, bov);
    attn_kernel<<<512, 256, 65536>>>();
    combine_kernel<<<1024, 256>>>();
    proj_kernel<<<dim3(128, 8), 256, 65536>>>(bo, out);
}